// round 6
// baseline (speedup 1.0000x reference)
#include <cuda_runtime.h>
#include <cuda_fp16.h>
#include <cstdint>

#define HIDDEN   1024
#define NLAYERS  20
#define M_TOTAL  8192

// ---- GEMM tiling (fp16 HMMA m16n8k16; A converted fp32->fp16 by producers) ----
#define BM 128
#define BN 128
#define BK 32                       // K per tile
#define KT (HIDDEN/BK)              // 32
#define ROWB 64                     // 32 halves = 64B rows (SW64), A and B alike
#define A_STAGE (BM*ROWB)           // 8192 B
#define B_STAGE (BN*ROWB)           // 8192 B
#define STAGE   (A_STAGE+B_STAGE)   // 16384 B
#define STAGES  3
#define SMEM_BYTES (STAGES*STAGE)   // 49152 B

__device__ __half g_wsum[HIDDEN*HIDDEN];     // 2 MB (pre-summed weights, fp16)

// ---------------------------------------------------------------------------
__device__ __forceinline__ uint32_t smem_u32(const void* p) {
    uint32_t a;
    asm("{ .reg .u64 t; cvta.to.shared.u64 t, %1; cvt.u32.u64 %0, t; }" : "=r"(a) : "l"(p));
    return a;
}
__device__ __forceinline__ void cp16(uint32_t saddr, const void* g) {
    asm volatile("cp.async.cg.shared.global [%0], [%1], 16;" :: "r"(saddr), "l"(g));
}
// pack two fp32 -> one fp16x2 register (lo = first arg)
__device__ __forceinline__ uint32_t f2_to_h2(float lo, float hi) {
    uint32_t r;
    asm("cvt.rn.f16x2.f32 %0, %1, %2;" : "=r"(r) : "f"(hi), "f"(lo));
    return r;
}
#define SW64(off) ((off) ^ (((off) >> 3) & 0x30u))

// ---------------------------------------------------------------------------
// Kernel 0: g_wsum = fp16(mean_l conv_w[l])   (80 MB read, 2 MB write)
// ---------------------------------------------------------------------------
__global__ void __launch_bounds__(256)
wsum_kernel(const float* __restrict__ cw) {
    const int i4 = blockIdx.x * 256 + threadIdx.x;   // 0..262143 (float4 idx)
    const float4* cw4 = (const float4*)cw;
    float4 a0 = cw4[i4];
    float4 a1 = cw4[(HIDDEN*HIDDEN/4) + i4];
#pragma unroll
    for (int l = 2; l < NLAYERS; l += 2) {
        float4 v0 = cw4[l       * (HIDDEN*HIDDEN/4) + i4];
        float4 v1 = cw4[(l + 1) * (HIDDEN*HIDDEN/4) + i4];
        a0.x += v0.x; a0.y += v0.y; a0.z += v0.z; a0.w += v0.w;
        a1.x += v1.x; a1.y += v1.y; a1.z += v1.z; a1.w += v1.w;
    }
    const float s = 1.0f / (float)NLAYERS;
    uint2 r;
    r.x = f2_to_h2((a0.x + a1.x) * s, (a0.y + a1.y) * s);
    r.y = f2_to_h2((a0.z + a1.z) * s, (a0.w + a1.w) * s);
    ((uint2*)g_wsum)[i4] = r;
}

// ---------------------------------------------------------------------------
// Kernel 1: out[m][n] = sum_k x[m][k] * Wsum[n][k]
//   A: LDG fp32 -> cvt -> STS fp16 (producer-side, once per element)
//   B: cp.async fp16 from g_wsum
//   Consumer: ldmatrix + mma.m16n8k16 (identical to the 62us-proven mainloop)
// ---------------------------------------------------------------------------
__global__ void __launch_bounds__(256, 2)
gemm_kernel(const float* __restrict__ x, float* __restrict__ out) {
    extern __shared__ char smem[];
    const uint32_t sbase = smem_u32(smem);

    const int tid  = threadIdx.x;
    const int lane = tid & 31;
    const int warp = tid >> 5;
    const int wm   = (warp & 1) * 64;
    const int wn   = (warp >> 1) * 32;
    const int mBase = blockIdx.y * BM;
    const int nBase = blockIdx.x * BN;

    // per-thread A chunk coords: 1024 float4-chunks per ktile, 4 per thread
    // chunk c: row = c>>3 (32 floats/row = 8 chunks), ch = c&7
    float4 rA[2][4];

    auto ldgA = [&](float4 (&dst)[4], int k0) {
#pragma unroll
        for (int i = 0; i < 4; ++i) {
            const int c = i * 256 + tid;
            const int row = c >> 3, ch = c & 7;
            dst[i] = *(const float4*)(x + (size_t)(mBase + row) * HIDDEN + k0 + ch * 4);
        }
    };
    auto stsA = [&](const float4 (&src)[4], int s) {
        char* sa = smem + (size_t)s * STAGE;
#pragma unroll
        for (int i = 0; i < 4; ++i) {
            const int c = i * 256 + tid;
            const int row = c >> 3, ch = c & 7;
            const uint32_t off = (uint32_t)(row * ROWB + ch * 8);
            uint2 h;
            h.x = f2_to_h2(src[i].x, src[i].y);
            h.y = f2_to_h2(src[i].z, src[i].w);
            *(uint2*)(sa + SW64(off)) = h;
        }
    };
    auto cpB = [&](int s, int k0) {
        const uint32_t sb = sbase + (uint32_t)s * STAGE + A_STAGE;
#pragma unroll
        for (int i = 0; i < 2; ++i) {
            const int c = i * 256 + tid;          // 512 chunks of 16B
            const int row = c >> 2, ch = c & 3;
            const uint32_t off = (uint32_t)(row * ROWB + ch * 16);
            cp16(sb + SW64(off), g_wsum + (size_t)(nBase + row) * HIDDEN + k0 + ch * 8);
        }
        asm volatile("cp.async.commit_group;");
    };

    float acc[4][4][4];
#pragma unroll
    for (int mi = 0; mi < 4; ++mi)
#pragma unroll
        for (int ni = 0; ni < 4; ++ni)
#pragma unroll
            for (int c = 0; c < 4; ++c) acc[mi][ni][c] = 0.0f;

    // ---- prologue ----
    {
        float4 t[4];
        ldgA(t, 0);      stsA(t, 0);
        ldgA(t, BK);     stsA(t, 1);
    }
    ldgA(rA[0], 2 * BK);
    ldgA(rA[1], 3 * BK);
    cpB(0, 0);
    cpB(1, BK);

    for (int kt = 0; kt < KT; ++kt) {
        asm volatile("cp.async.wait_group 1;");
        __syncthreads();

        if (kt + 2 < KT) {
            stsA(rA[kt & 1], (kt + 2) % STAGES);
            cpB((kt + 2) % STAGES, (kt + 2) * BK);
        } else {
            asm volatile("cp.async.commit_group;");
        }
        if (kt + 4 < KT) ldgA(rA[kt & 1], (kt + 4) * BK);

        const uint32_t sa = sbase + (uint32_t)(kt % STAGES) * STAGE;
        const uint32_t sb = sa + A_STAGE;

#pragma unroll
        for (int kk = 0; kk < 2; ++kk) {        // two k=16 chunks
            uint32_t af[4][4], bf[2][4];
            const uint32_t colb = (uint32_t)(kk * 32 + (lane >> 4) * 16);
#pragma unroll
            for (int mi = 0; mi < 4; ++mi) {
                const uint32_t off = (uint32_t)((wm + mi * 16 + (lane & 15)) * ROWB) + colb;
                asm volatile("ldmatrix.sync.aligned.m8n8.x4.shared.b16 {%0,%1,%2,%3}, [%4];"
                             : "=r"(af[mi][0]), "=r"(af[mi][1]), "=r"(af[mi][2]), "=r"(af[mi][3])
                             : "r"(sa + SW64(off)));
            }
#pragma unroll
            for (int np = 0; np < 2; ++np) {
                const uint32_t off = (uint32_t)((wn + np * 16 + (lane & 15)) * ROWB) + colb;
                asm volatile("ldmatrix.sync.aligned.m8n8.x4.shared.b16 {%0,%1,%2,%3}, [%4];"
                             : "=r"(bf[np][0]), "=r"(bf[np][1]), "=r"(bf[np][2]), "=r"(bf[np][3])
                             : "r"(sb + SW64(off)));
            }
#pragma unroll
            for (int mi = 0; mi < 4; ++mi) {
#pragma unroll
                for (int np = 0; np < 2; ++np) {
                    asm volatile(
                        "mma.sync.aligned.m16n8k16.row.col.f32.f16.f16.f32 "
                        "{%0,%1,%2,%3}, {%4,%5,%6,%7}, {%8,%9}, {%0,%1,%2,%3};"
                        : "+f"(acc[mi][np*2][0]), "+f"(acc[mi][np*2][1]),
                          "+f"(acc[mi][np*2][2]), "+f"(acc[mi][np*2][3])
                        : "r"(af[mi][0]), "r"(af[mi][1]), "r"(af[mi][2]), "r"(af[mi][3]),
                          "r"(bf[np][0]), "r"(bf[np][2]));
                    asm volatile(
                        "mma.sync.aligned.m16n8k16.row.col.f32.f16.f16.f32 "
                        "{%0,%1,%2,%3}, {%4,%5,%6,%7}, {%8,%9}, {%0,%1,%2,%3};"
                        : "+f"(acc[mi][np*2+1][0]), "+f"(acc[mi][np*2+1][1]),
                          "+f"(acc[mi][np*2+1][2]), "+f"(acc[mi][np*2+1][3])
                        : "r"(af[mi][0]), "r"(af[mi][1]), "r"(af[mi][2]), "r"(af[mi][3]),
                          "r"(bf[np][1]), "r"(bf[np][3]));
                }
            }
        }
    }

    // ---- epilogue ----
    const int r0 = mBase + wm + (lane >> 2);
    const int c0 = nBase + wn + (lane & 3) * 2;
#pragma unroll
    for (int mi = 0; mi < 4; ++mi) {
#pragma unroll
        for (int ni = 0; ni < 4; ++ni) {
            const int r = r0 + mi * 16;
            const int c = c0 + ni * 8;
            *(float2*)(out + (size_t)r * HIDDEN + c)       = make_float2(acc[mi][ni][0], acc[mi][ni][1]);
            *(float2*)(out + (size_t)(r + 8) * HIDDEN + c) = make_float2(acc[mi][ni][2], acc[mi][ni][3]);
        }
    }
}

// ---------------------------------------------------------------------------
// Kernel 2: in-place RMS-norm:  x * sqrt(H) / sqrt(sum x^2 + EPS*H) * w
// ---------------------------------------------------------------------------
__global__ void __launch_bounds__(256)
rmsnorm_kernel(float* __restrict__ out, const float* __restrict__ nw) {
    const int row = blockIdx.x;
    float4* p = (float4*)(out + (size_t)row * HIDDEN);
    float4 v = p[threadIdx.x];

    float ss = v.x * v.x + v.y * v.y + v.z * v.z + v.w * v.w;
#pragma unroll
    for (int o = 16; o > 0; o >>= 1) ss += __shfl_xor_sync(0xFFFFFFFFu, ss, o);

    __shared__ float wsum[8];
    __shared__ float s_scale;
    if ((threadIdx.x & 31) == 0) wsum[threadIdx.x >> 5] = ss;
    __syncthreads();
    if (threadIdx.x == 0) {
        float t = 0.0f;
#pragma unroll
        for (int i = 0; i < 8; ++i) t += wsum[i];
        s_scale = 32.0f * rsqrtf(t + 1.024e-3f);
    }
    __syncthreads();
    const float sc = s_scale;

    float4 w = ((const float4*)nw)[threadIdx.x];
    v.x = v.x * sc * w.x;
    v.y = v.y * sc * w.y;
    v.z = v.z * sc * w.z;
    v.w = v.w * sc * w.w;
    p[threadIdx.x] = v;
}

// ---------------------------------------------------------------------------
extern "C" void kernel_launch(void* const* d_in, const int* in_sizes, int n_in,
                              void* d_out, int out_size) {
    const float* x  = (const float*)d_in[0];   // [2,4096,1024] fp32
    const float* cw = (const float*)d_in[1];   // [20,1024,1024] fp32
    const float* nw = (const float*)d_in[2];   // [1024] fp32
    float* out = (float*)d_out;                // [2,4096,1024] fp32
    (void)in_sizes; (void)n_in; (void)out_size;

    wsum_kernel<<<HIDDEN*HIDDEN/4/256, 256>>>(cw);

    cudaFuncSetAttribute(gemm_kernel, cudaFuncAttributeMaxDynamicSharedMemorySize, SMEM_BYTES);
    dim3 grid(HIDDEN / BN, M_TOTAL / BM);   // (8, 64) = 512 CTAs
    gemm_kernel<<<grid, 256, SMEM_BYTES>>>(x, out);

    rmsnorm_kernel<<<M_TOTAL, 256>>>(out, nw);
}

// round 7
// speedup vs baseline: 1.2787x; 1.2787x over previous
#include <cuda_runtime.h>
#include <cuda_fp16.h>
#include <cstdint>

#define HIDDEN   1024
#define NLAYERS  20
#define M_TOTAL  8192

// ---- GEMM tiling (fp16 HMMA m16n8k16; A converted fp32->fp16 by producers) ----
#define BM 128
#define BN 128
#define BK 32                       // K per tile
#define KT (HIDDEN/BK)              // 32
#define ROWB 64                     // 32 halves = 64B rows (SW64), A and B alike
#define A_STAGE (BM*ROWB)           // 8192 B
#define B_STAGE (BN*ROWB)           // 8192 B
#define STAGE   (A_STAGE+B_STAGE)   // 16384 B
#define STAGES  3
#define SMEM_BYTES (STAGES*STAGE)   // 49152 B

__device__ __half g_wsum[HIDDEN*HIDDEN];     // 2 MB (pre-summed weights, fp16)

// ---------------------------------------------------------------------------
__device__ __forceinline__ uint32_t smem_u32(const void* p) {
    uint32_t a;
    asm("{ .reg .u64 t; cvta.to.shared.u64 t, %1; cvt.u32.u64 %0, t; }" : "=r"(a) : "l"(p));
    return a;
}
__device__ __forceinline__ void cp16(uint32_t saddr, const void* g) {
    asm volatile("cp.async.cg.shared.global [%0], [%1], 16;" :: "r"(saddr), "l"(g));
}
// pack two fp32 -> one fp16x2 register (lo = first arg)
__device__ __forceinline__ uint32_t f2_to_h2(float lo, float hi) {
    uint32_t r;
    asm("cvt.rn.f16x2.f32 %0, %1, %2;" : "=r"(r) : "f"(hi), "f"(lo));
    return r;
}
#define SW64(off) ((off) ^ (((off) >> 3) & 0x30u))

// ---------------------------------------------------------------------------
// Kernel 0: g_wsum = fp16(mean_l conv_w[l])  — MLP-4 restructure
// ---------------------------------------------------------------------------
__global__ void __launch_bounds__(256)
wsum_kernel(const float* __restrict__ cw) {
    const int i4 = blockIdx.x * 256 + threadIdx.x;   // 0..262143 (float4 idx)
    const float4* cw4 = (const float4*)cw;
    const int LSTR = HIDDEN * HIDDEN / 4;

    float4 a0 = cw4[i4];
    float4 a1 = cw4[LSTR + i4];
    float4 a2 = cw4[2 * LSTR + i4];
    float4 a3 = cw4[3 * LSTR + i4];
#pragma unroll
    for (int l = 4; l < NLAYERS; l += 4) {
        float4 v0 = cw4[(l + 0) * LSTR + i4];
        float4 v1 = cw4[(l + 1) * LSTR + i4];
        float4 v2 = cw4[(l + 2) * LSTR + i4];
        float4 v3 = cw4[(l + 3) * LSTR + i4];
        a0.x += v0.x; a0.y += v0.y; a0.z += v0.z; a0.w += v0.w;
        a1.x += v1.x; a1.y += v1.y; a1.z += v1.z; a1.w += v1.w;
        a2.x += v2.x; a2.y += v2.y; a2.z += v2.z; a2.w += v2.w;
        a3.x += v3.x; a3.y += v3.y; a3.z += v3.z; a3.w += v3.w;
    }
    a0.x += a2.x; a0.y += a2.y; a0.z += a2.z; a0.w += a2.w;
    a1.x += a3.x; a1.y += a3.y; a1.z += a3.z; a1.w += a3.w;
    const float s = 1.0f / (float)NLAYERS;
    uint2 r;
    r.x = f2_to_h2((a0.x + a1.x) * s, (a0.y + a1.y) * s);
    r.y = f2_to_h2((a0.z + a1.z) * s, (a0.w + a1.w) * s);
    ((uint2*)g_wsum)[i4] = r;
}

// ---------------------------------------------------------------------------
// Kernel 1: out[m][n] = sum_k x[m][k] * Wsum[n][k]
//   A: LDG fp32 -> cvt -> STS fp16 (producer-side, single register buffer)
//   B: cp.async fp16 from g_wsum
//   Consumer: ldmatrix + mma.m16n8k16 (R3's proven 62us mainloop)
// ---------------------------------------------------------------------------
__global__ void __launch_bounds__(256, 2)
gemm_kernel(const float* __restrict__ x, float* __restrict__ out) {
    extern __shared__ char smem[];
    const uint32_t sbase = smem_u32(smem);

    const int tid  = threadIdx.x;
    const int lane = tid & 31;
    const int warp = tid >> 5;
    const int wm   = (warp & 1) * 64;
    const int wn   = (warp >> 1) * 32;
    const int mBase = blockIdx.y * BM;
    const int nBase = blockIdx.x * BN;

    float4 rA[4];   // single in-flight A buffer (16 regs)

    auto ldgA = [&](int k0) {
#pragma unroll
        for (int i = 0; i < 4; ++i) {
            const int c = i * 256 + tid;
            const int row = c >> 3, ch = c & 7;
            rA[i] = *(const float4*)(x + (size_t)(mBase + row) * HIDDEN + k0 + ch * 4);
        }
    };
    auto stsA = [&](int s) {
        char* sa = smem + (size_t)s * STAGE;
#pragma unroll
        for (int i = 0; i < 4; ++i) {
            const int c = i * 256 + tid;
            const int row = c >> 3, ch = c & 7;
            const uint32_t off = (uint32_t)(row * ROWB + ch * 8);
            uint2 h;
            h.x = f2_to_h2(rA[i].x, rA[i].y);
            h.y = f2_to_h2(rA[i].z, rA[i].w);
            *(uint2*)(sa + SW64(off)) = h;
        }
    };
    auto cpB = [&](int s, int k0) {
        const uint32_t sb = sbase + (uint32_t)s * STAGE + A_STAGE;
#pragma unroll
        for (int i = 0; i < 2; ++i) {
            const int c = i * 256 + tid;          // 512 chunks of 16B
            const int row = c >> 2, ch = c & 3;
            const uint32_t off = (uint32_t)(row * ROWB + ch * 16);
            cp16(sb + SW64(off), g_wsum + (size_t)(nBase + row) * HIDDEN + k0 + ch * 8);
        }
        asm volatile("cp.async.commit_group;");
    };

    float acc[4][4][4];
#pragma unroll
    for (int mi = 0; mi < 4; ++mi)
#pragma unroll
        for (int ni = 0; ni < 4; ++ni)
#pragma unroll
            for (int c = 0; c < 4; ++c) acc[mi][ni][c] = 0.0f;

    // ---- prologue: stages 0,1 direct; rA holds ktile 2 ----
    ldgA(0);      stsA(0);
    ldgA(BK);     stsA(1);
    ldgA(2 * BK);
    cpB(0, 0);
    cpB(1, BK);

    for (int kt = 0; kt < KT; ++kt) {
        asm volatile("cp.async.wait_group 1;");
        __syncthreads();

        if (kt + 2 < KT) {
            stsA((kt + 2) % STAGES);            // rA = ktile kt+2
            cpB((kt + 2) % STAGES, (kt + 2) * BK);
        } else {
            asm volatile("cp.async.commit_group;");
        }
        if (kt + 3 < KT) ldgA((kt + 3) * BK);   // refill rA for next iteration

        const uint32_t sa = sbase + (uint32_t)(kt % STAGES) * STAGE;
        const uint32_t sb = sa + A_STAGE;

#pragma unroll
        for (int kk = 0; kk < 2; ++kk) {        // two k=16 chunks
            uint32_t af[4][4], bf[2][4];
            const uint32_t colb = (uint32_t)(kk * 32 + (lane >> 4) * 16);
#pragma unroll
            for (int mi = 0; mi < 4; ++mi) {
                const uint32_t off = (uint32_t)((wm + mi * 16 + (lane & 15)) * ROWB) + colb;
                asm volatile("ldmatrix.sync.aligned.m8n8.x4.shared.b16 {%0,%1,%2,%3}, [%4];"
                             : "=r"(af[mi][0]), "=r"(af[mi][1]), "=r"(af[mi][2]), "=r"(af[mi][3])
                             : "r"(sa + SW64(off)));
            }
#pragma unroll
            for (int np = 0; np < 2; ++np) {
                const uint32_t off = (uint32_t)((wn + np * 16 + (lane & 15)) * ROWB) + colb;
                asm volatile("ldmatrix.sync.aligned.m8n8.x4.shared.b16 {%0,%1,%2,%3}, [%4];"
                             : "=r"(bf[np][0]), "=r"(bf[np][1]), "=r"(bf[np][2]), "=r"(bf[np][3])
                             : "r"(sb + SW64(off)));
            }
#pragma unroll
            for (int mi = 0; mi < 4; ++mi) {
#pragma unroll
                for (int np = 0; np < 2; ++np) {
                    asm volatile(
                        "mma.sync.aligned.m16n8k16.row.col.f32.f16.f16.f32 "
                        "{%0,%1,%2,%3}, {%4,%5,%6,%7}, {%8,%9}, {%0,%1,%2,%3};"
                        : "+f"(acc[mi][np*2][0]), "+f"(acc[mi][np*2][1]),
                          "+f"(acc[mi][np*2][2]), "+f"(acc[mi][np*2][3])
                        : "r"(af[mi][0]), "r"(af[mi][1]), "r"(af[mi][2]), "r"(af[mi][3]),
                          "r"(bf[np][0]), "r"(bf[np][2]));
                    asm volatile(
                        "mma.sync.aligned.m16n8k16.row.col.f32.f16.f16.f32 "
                        "{%0,%1,%2,%3}, {%4,%5,%6,%7}, {%8,%9}, {%0,%1,%2,%3};"
                        : "+f"(acc[mi][np*2+1][0]), "+f"(acc[mi][np*2+1][1]),
                          "+f"(acc[mi][np*2+1][2]), "+f"(acc[mi][np*2+1][3])
                        : "r"(af[mi][0]), "r"(af[mi][1]), "r"(af[mi][2]), "r"(af[mi][3]),
                          "r"(bf[np][1]), "r"(bf[np][3]));
                }
            }
        }
    }

    // ---- epilogue ----
    const int r0 = mBase + wm + (lane >> 2);
    const int c0 = nBase + wn + (lane & 3) * 2;
#pragma unroll
    for (int mi = 0; mi < 4; ++mi) {
#pragma unroll
        for (int ni = 0; ni < 4; ++ni) {
            const int r = r0 + mi * 16;
            const int c = c0 + ni * 8;
            *(float2*)(out + (size_t)r * HIDDEN + c)       = make_float2(acc[mi][ni][0], acc[mi][ni][1]);
            *(float2*)(out + (size_t)(r + 8) * HIDDEN + c) = make_float2(acc[mi][ni][2], acc[mi][ni][3]);
        }
    }
}

// ---------------------------------------------------------------------------
// Kernel 2: in-place RMS-norm:  x * sqrt(H) / sqrt(sum x^2 + EPS*H) * w
// ---------------------------------------------------------------------------
__global__ void __launch_bounds__(256)
rmsnorm_kernel(float* __restrict__ out, const float* __restrict__ nw) {
    const int row = blockIdx.x;
    float4* p = (float4*)(out + (size_t)row * HIDDEN);
    float4 v = p[threadIdx.x];

    float ss = v.x * v.x + v.y * v.y + v.z * v.z + v.w * v.w;
#pragma unroll
    for (int o = 16; o > 0; o >>= 1) ss += __shfl_xor_sync(0xFFFFFFFFu, ss, o);

    __shared__ float wsum[8];
    __shared__ float s_scale;
    if ((threadIdx.x & 31) == 0) wsum[threadIdx.x >> 5] = ss;
    __syncthreads();
    if (threadIdx.x == 0) {
        float t = 0.0f;
#pragma unroll
        for (int i = 0; i < 8; ++i) t += wsum[i];
        s_scale = 32.0f * rsqrtf(t + 1.024e-3f);
    }
    __syncthreads();
    const float sc = s_scale;

    float4 w = ((const float4*)nw)[threadIdx.x];
    v.x = v.x * sc * w.x;
    v.y = v.y * sc * w.y;
    v.z = v.z * sc * w.z;
    v.w = v.w * sc * w.w;
    p[threadIdx.x] = v;
}

// ---------------------------------------------------------------------------
extern "C" void kernel_launch(void* const* d_in, const int* in_sizes, int n_in,
                              void* d_out, int out_size) {
    const float* x  = (const float*)d_in[0];   // [2,4096,1024] fp32
    const float* cw = (const float*)d_in[1];   // [20,1024,1024] fp32
    const float* nw = (const float*)d_in[2];   // [1024] fp32
    float* out = (float*)d_out;                // [2,4096,1024] fp32
    (void)in_sizes; (void)n_in; (void)out_size;

    wsum_kernel<<<HIDDEN*HIDDEN/4/256, 256>>>(cw);

    cudaFuncSetAttribute(gemm_kernel, cudaFuncAttributeMaxDynamicSharedMemorySize, SMEM_BYTES);
    dim3 grid(HIDDEN / BN, M_TOTAL / BM);   // (8, 64) = 512 CTAs
    gemm_kernel<<<grid, 256, SMEM_BYTES>>>(x, out);

    rmsnorm_kernel<<<M_TOTAL, 256>>>(out, nw);
}